// round 2
// baseline (speedup 1.0000x reference)
#include <cuda_runtime.h>
#include <math.h>

// ---------------- Problem constants ----------------
#define T_TOK  8192          // B*S tokens
#define DM     1024          // d_model
#define DFF    2048          // d_ff
#define NE     16            // experts
#define TOPK   2
#define CAP    1280          // int(1.25 * T*K / E)
#define EC     (NE*CAP)      // 20480 padded rows

// ---------------- Scratch (device globals; no allocations) ----------------
__device__ int   g_sel [T_TOK*TOPK];
__device__ float g_wt  [T_TOK*TOPK];
__device__ int   g_slot[T_TOK*TOPK];     // dest slot or -1
__device__ int   g_src [EC];             // flat assignment index or -1
__device__ float g_X   [(size_t)EC*DM];  // padded expert inputs   (~80 MB)
__device__ float g_H   [(size_t)EC*DFF]; // hidden after gelu      (~160 MB)
__device__ float g_Y   [(size_t)EC*DM];  // expert outputs         (~80 MB)

// ---------------- Helpers ----------------
__device__ __forceinline__ unsigned long long fma2(unsigned long long a,
                                                   unsigned long long b,
                                                   unsigned long long c) {
    unsigned long long d;
    asm("fma.rn.f32x2 %0, %1, %2, %3;" : "=l"(d) : "l"(a), "l"(b), "l"(c));
    return d;
}

__device__ __forceinline__ float2 up2(unsigned long long v) {
    float2 r;
    r.x = __uint_as_float((unsigned int)(v & 0xffffffffull));
    r.y = __uint_as_float((unsigned int)(v >> 32));
    return r;
}

__device__ __forceinline__ float gelu_f(float x) {
    return 0.5f * x * (1.0f + erff(x * 0.70710678118654752440f));
}

// ---------------- 1) Gate: logits -> sigmoid -> top2 -> weights ----------------
// one warp per token; 8 warps per block
__global__ void gate_kernel(const float* __restrict__ x, const float* __restrict__ gw) {
    const int warp = threadIdx.x >> 5, lane = threadIdx.x & 31;
    const int t = blockIdx.x * 8 + warp;
    const float* xr = x + (size_t)t * DM;

    float xv[32];
#pragma unroll
    for (int j = 0; j < 32; j++) xv[j] = xr[lane + 32 * j];

    float logits[NE];
#pragma unroll
    for (int e = 0; e < NE; e++) {
        const float* g = gw + e * DM;
        float s = 0.f;
#pragma unroll
        for (int j = 0; j < 32; j++) s += xv[j] * g[lane + 32 * j];
#pragma unroll
        for (int o = 16; o > 0; o >>= 1) s += __shfl_xor_sync(0xffffffffu, s, o);
        logits[e] = s;
    }

    if (lane == 0) {
        float v0 = -1e30f, v1 = -1e30f;
        int i0 = 0, i1 = 0;
#pragma unroll
        for (int e = 0; e < NE; e++) {
            float p = 1.0f / (1.0f + expf(-logits[e]));
            if (p > v0)      { v1 = v0; i1 = i0; v0 = p; i0 = e; }
            else if (p > v1) { v1 = p;  i1 = e; }
        }
        float s = v0 + v1 + 1e-6f;
        g_sel[2 * t]     = i0;
        g_sel[2 * t + 1] = i1;
        g_wt [2 * t]     = v0 / s;
        g_wt [2 * t + 1] = v1 / s;
    }
}

// ---------------- 2) Ordered capacity ranking (token-major cumsum) ----------------
// one block per expert; deterministic, matches jax cumsum over one-hot
__global__ void rank_kernel() {
    const int e = blockIdx.x;
    const int tid = threadIdx.x;
    const int ITEMS = (T_TOK * TOPK) / 256;  // 64 contiguous items/thread
    const int base = tid * ITEMS;

    int cnt = 0;
    for (int i = 0; i < ITEMS; i++) cnt += (g_sel[base + i] == e);

    __shared__ int s[256];
    s[tid] = cnt;
    __syncthreads();

    int off = 0, tot = 0;
    for (int j = 0; j < 256; j++) { int v = s[j]; tot += v; if (j < tid) off += v; }

    int r = off;
    for (int i = 0; i < ITEMS; i++) {
        int idx = base + i;
        if (g_sel[idx] == e) {
            if (r < CAP) {
                g_slot[idx] = e * CAP + r;
                g_src[e * CAP + r] = idx;
            } else {
                g_slot[idx] = -1;
            }
            r++;
        }
    }
    int filled = tot < CAP ? tot : CAP;
    for (int r2 = filled + tid; r2 < CAP; r2 += 256) g_src[e * CAP + r2] = -1;
}

// ---------------- 3) Gather / pad expert inputs ----------------
__global__ void gather_kernel(const float* __restrict__ x) {
    const int row = blockIdx.x;
    const int src = g_src[row];
    float4* dst = ((float4*)g_X) + (size_t)row * (DM / 4);
    if (src >= 0) {
        const int tok = src >> 1;  // flat idx / TOPK
        const float4* s4 = ((const float4*)x) + (size_t)tok * (DM / 4);
        for (int i = threadIdx.x; i < DM / 4; i += blockDim.x) dst[i] = s4[i];
    } else {
        float4 z = make_float4(0.f, 0.f, 0.f, 0.f);
        for (int i = threadIdx.x; i < DM / 4; i += blockDim.x) dst[i] = z;
    }
}

// ---------------- 4/5) Batched expert GEMM (fp32, packed f32x2 FMA) ----------------
// Tile 128x128x8, 256 threads, 8x8 micro-tile held as 8x4 f32x2 pairs.
// PHASE 0: g_H = gelu(g_X @ w1[e])   (KD=1024, ND=2048)
// PHASE 1: g_Y =       g_H @ w2[e]   (KD=2048, ND=1024)
#define BM 128
#define BN 128
#define BKT 8

template <int KD, int ND, int ACT, int PHASE>
__global__ __launch_bounds__(256) void gemm_kernel(const float* __restrict__ Bg) {
    const float* A = (PHASE == 0 ? g_X : g_H) + (size_t)blockIdx.z * CAP * KD;
    const float* B = Bg + (size_t)blockIdx.z * KD * ND;
    float*       C = (PHASE == 0 ? g_H : g_Y) + (size_t)blockIdx.z * CAP * ND;

    const int m0 = blockIdx.y * BM;
    const int n0 = blockIdx.x * BN;
    const int tid = threadIdx.x;
    const int ty = tid >> 4, tx = tid & 15;

    __shared__ float As2[BKT][2 * BM];  // each A value duplicated -> direct pair loads
    __shared__ float Bs [BKT][BN];

    unsigned long long acc[8][4];
#pragma unroll
    for (int i = 0; i < 8; i++)
#pragma unroll
        for (int j = 0; j < 4; j++) acc[i][j] = 0ull;

    const int am = tid >> 1, akq = tid & 1;   // A: 128 rows x 2 float4 along k
    const int bk = tid >> 5, bn = tid & 31;   // B: 8 rows x 32 float4 along n

    const float* Aptr = A + (size_t)(m0 + am) * KD + 4 * akq;
    const float* Bptr = B + (size_t)bk * ND + n0 + 4 * bn;

    for (int kt = 0; kt < KD; kt += BKT) {
        const float4 ga = *(const float4*)(Aptr + kt);
        const float4 gb = *(const float4*)(Bptr + (size_t)kt * ND);

        __syncthreads();  // previous tile fully consumed
        As2[4 * akq + 0][2 * am] = ga.x; As2[4 * akq + 0][2 * am + 1] = ga.x;
        As2[4 * akq + 1][2 * am] = ga.y; As2[4 * akq + 1][2 * am + 1] = ga.y;
        As2[4 * akq + 2][2 * am] = ga.z; As2[4 * akq + 2][2 * am + 1] = ga.z;
        As2[4 * akq + 3][2 * am] = ga.w; As2[4 * akq + 3][2 * am + 1] = ga.w;
        *(float4*)&Bs[bk][4 * bn] = gb;
        __syncthreads();

#pragma unroll
        for (int kk = 0; kk < BKT; kk++) {
            const ulonglong2* ap = (const ulonglong2*)&As2[kk][16 * ty];
            ulonglong2 a0 = ap[0], a1 = ap[1], a2 = ap[2], a3 = ap[3];
            const ulonglong2* bp = (const ulonglong2*)&Bs[kk][8 * tx];
            ulonglong2 b0 = bp[0], b1 = bp[1];
            unsigned long long av[8] = {a0.x, a0.y, a1.x, a1.y, a2.x, a2.y, a3.x, a3.y};
            unsigned long long bv[4] = {b0.x, b0.y, b1.x, b1.y};
#pragma unroll
            for (int i = 0; i < 8; i++)
#pragma unroll
                for (int j = 0; j < 4; j++)
                    acc[i][j] = fma2(av[i], bv[j], acc[i][j]);
        }
    }

#pragma unroll
    for (int i = 0; i < 8; i++) {
        const int row = m0 + ty * 8 + i;
        float v[8];
#pragma unroll
        for (int j = 0; j < 4; j++) {
            float2 p = up2(acc[i][j]);
            v[2 * j] = p.x; v[2 * j + 1] = p.y;
        }
        if (ACT) {
#pragma unroll
            for (int j = 0; j < 8; j++) v[j] = gelu_f(v[j]);
        }
        float* cp = C + (size_t)row * ND + n0 + tx * 8;
        *(float4*)cp       = make_float4(v[0], v[1], v[2], v[3]);
        *(float4*)(cp + 4) = make_float4(v[4], v[5], v[6], v[7]);
    }
}

// ---------------- 6) Combine ----------------
__global__ void combine_kernel(float* __restrict__ out) {
    const int t = blockIdx.x;
    const int s0 = g_slot[2 * t], s1 = g_slot[2 * t + 1];
    const float w0 = g_wt[2 * t], w1 = g_wt[2 * t + 1];
    float4* o = ((float4*)out) + (size_t)t * (DM / 4);
    const float4* Y4 = (const float4*)g_Y;
    for (int i = threadIdx.x; i < DM / 4; i += blockDim.x) {
        float4 r = make_float4(0.f, 0.f, 0.f, 0.f);
        if (s0 >= 0) {
            float4 y = Y4[(size_t)s0 * (DM / 4) + i];
            r.x += w0 * y.x; r.y += w0 * y.y; r.z += w0 * y.z; r.w += w0 * y.w;
        }
        if (s1 >= 0) {
            float4 y = Y4[(size_t)s1 * (DM / 4) + i];
            r.x += w1 * y.x; r.y += w1 * y.y; r.z += w1 * y.z; r.w += w1 * y.w;
        }
        o[i] = r;
    }
}

// ---------------- Launch ----------------
extern "C" void kernel_launch(void* const* d_in, const int* in_sizes, int n_in,
                              void* d_out, int out_size) {
    (void)in_sizes; (void)n_in; (void)out_size;
    const float* x  = (const float*)d_in[0];   // [8192, 1024]
    const float* gw = (const float*)d_in[1];   // [16, 1024]
    const float* w1 = (const float*)d_in[2];   // [16, 1024, 2048]
    const float* w2 = (const float*)d_in[3];   // [16, 2048, 1024]
    float* out = (float*)d_out;                // [8192, 1024] fp32

    gate_kernel<<<T_TOK / 8, 256>>>(x, gw);
    rank_kernel<<<NE, 256>>>();
    gather_kernel<<<EC, 128>>>(x);
    gemm_kernel<DM,  DFF, 1, 0><<<dim3(DFF / BN, CAP / BM, NE), 256>>>(w1);
    gemm_kernel<DFF, DM,  0, 1><<<dim3(DM  / BN, CAP / BM, NE), 256>>>(w2);
    combine_kernel<<<T_TOK, 256>>>(out);
}

// round 4
// speedup vs baseline: 3.0588x; 3.0588x over previous
#include <cuda_runtime.h>
#include <cuda_bf16.h>
#include <math.h>
#include <stdint.h>

// ---------------- Problem constants ----------------
#define T_TOK  8192
#define DM     1024
#define DFF    2048
#define NE     16
#define TOPK   2
#define CAP    1280
#define EC     (NE*CAP)

// ---------------- Scratch (device globals; no allocations) ----------------
__device__ int   g_sel [T_TOK*TOPK];
__device__ float g_wt  [T_TOK*TOPK];
__device__ int   g_slot[T_TOK*TOPK];
__device__ int   g_src [EC];
__device__ __nv_bfloat16 g_Xhi[(size_t)EC*DM];
__device__ __nv_bfloat16 g_Xlo[(size_t)EC*DM];
__device__ __nv_bfloat16 g_Hhi[(size_t)EC*DFF];
__device__ __nv_bfloat16 g_Hlo[(size_t)EC*DFF];
__device__ __nv_bfloat16 g_W1hi[(size_t)NE*DFF*DM];   // [E][N=DFF][K=DM] (K-major)
__device__ __nv_bfloat16 g_W1lo[(size_t)NE*DFF*DM];
__device__ __nv_bfloat16 g_W2hi[(size_t)NE*DM*DFF];   // [E][N=DM][K=DFF]
__device__ __nv_bfloat16 g_W2lo[(size_t)NE*DM*DFF];
__device__ float g_Y[(size_t)EC*DM];

// ---------------- PTX helpers (baseline ISA only: no 'a'-gated instrs) ----------------
__device__ __forceinline__ uint32_t smem_u32(const void* p) {
    uint32_t a;
    asm("{ .reg .u64 t; cvta.to.shared.u64 t, %1; cvt.u32.u64 %0, t; }" : "=r"(a) : "l"(p));
    return a;
}
__device__ __forceinline__ void cp16(uint32_t dst, const void* src) {
    asm volatile("cp.async.cg.shared.global [%0], [%1], 16;" :: "r"(dst), "l"(src));
}
#define CP_COMMIT() asm volatile("cp.async.commit_group;" ::: "memory")
template <int N>
__device__ __forceinline__ void cp_wait() {
    asm volatile("cp.async.wait_group %0;" :: "n"(N) : "memory");
}

__device__ __forceinline__ void ldsm4(uint32_t* r, uint32_t addr) {
    asm volatile("ldmatrix.sync.aligned.m8n8.x4.shared.b16 {%0,%1,%2,%3}, [%4];"
        : "=r"(r[0]), "=r"(r[1]), "=r"(r[2]), "=r"(r[3]) : "r"(addr));
}
__device__ __forceinline__ void mma16816(float* c, const uint32_t* a, uint32_t b0, uint32_t b1) {
    asm volatile("mma.sync.aligned.m16n8k16.row.col.f32.bf16.bf16.f32 "
        "{%0,%1,%2,%3}, {%4,%5,%6,%7}, {%8,%9}, {%0,%1,%2,%3};"
        : "+f"(c[0]), "+f"(c[1]), "+f"(c[2]), "+f"(c[3])
        : "r"(a[0]), "r"(a[1]), "r"(a[2]), "r"(a[3]), "r"(b0), "r"(b1));
}

__device__ __forceinline__ float gelu_f(float x) {
    return 0.5f * x * (1.0f + erff(x * 0.70710678118654752440f));
}

// ---------------- 1) Gate ----------------
__global__ void gate_kernel(const float* __restrict__ x, const float* __restrict__ gw) {
    const int warp = threadIdx.x >> 5, lane = threadIdx.x & 31;
    const int t = blockIdx.x * 8 + warp;
    const float* xr = x + (size_t)t * DM;
    float xv[32];
#pragma unroll
    for (int j = 0; j < 32; j++) xv[j] = xr[lane + 32 * j];
    float logits[NE];
#pragma unroll
    for (int e = 0; e < NE; e++) {
        const float* g = gw + e * DM;
        float s = 0.f;
#pragma unroll
        for (int j = 0; j < 32; j++) s += xv[j] * g[lane + 32 * j];
#pragma unroll
        for (int o = 16; o > 0; o >>= 1) s += __shfl_xor_sync(0xffffffffu, s, o);
        logits[e] = s;
    }
    if (lane == 0) {
        float v0 = -1e30f, v1 = -1e30f; int i0 = 0, i1 = 0;
#pragma unroll
        for (int e = 0; e < NE; e++) {
            float p = 1.0f / (1.0f + expf(-logits[e]));
            if (p > v0)      { v1 = v0; i1 = i0; v0 = p; i0 = e; }
            else if (p > v1) { v1 = p;  i1 = e; }
        }
        float s = v0 + v1 + 1e-6f;
        g_sel[2*t] = i0; g_sel[2*t+1] = i1;
        g_wt [2*t] = v0 / s; g_wt [2*t+1] = v1 / s;
    }
}

// ---------------- 2) Ordered capacity ranking ----------------
__global__ void rank_kernel() {
    const int e = blockIdx.x, tid = threadIdx.x;
    const int ITEMS = (T_TOK * TOPK) / 256;
    const int base = tid * ITEMS;
    int cnt = 0;
    for (int i = 0; i < ITEMS; i++) cnt += (g_sel[base + i] == e);
    __shared__ int s[256];
    s[tid] = cnt;
    __syncthreads();
    int off = 0, tot = 0;
    for (int j = 0; j < 256; j++) { int v = s[j]; tot += v; if (j < tid) off += v; }
    int r = off;
    for (int i = 0; i < ITEMS; i++) {
        int idx = base + i;
        if (g_sel[idx] == e) {
            if (r < CAP) { g_slot[idx] = e * CAP + r; g_src[e * CAP + r] = idx; }
            else g_slot[idx] = -1;
            r++;
        }
    }
    int filled = tot < CAP ? tot : CAP;
    for (int r2 = filled + tid; r2 < CAP; r2 += 256) g_src[e * CAP + r2] = -1;
}

// ---------------- 3) Gather + bf16 hi/lo split of X ----------------
__global__ void gather_split_kernel(const float* __restrict__ x) {
    const int row = blockIdx.x;
    const int src = g_src[row];
    __nv_bfloat162* hi = (__nv_bfloat162*)(g_Xhi + (size_t)row * DM);
    __nv_bfloat162* lo = (__nv_bfloat162*)(g_Xlo + (size_t)row * DM);
    if (src >= 0) {
        const float2* s = (const float2*)(x + (size_t)(src >> 1) * DM);
        for (int i = threadIdx.x; i < DM / 2; i += 128) {
            float2 v = s[i];
            __nv_bfloat16 h0 = __float2bfloat16(v.x), h1 = __float2bfloat16(v.y);
            __nv_bfloat16 l0 = __float2bfloat16(v.x - __bfloat162float(h0));
            __nv_bfloat16 l1 = __float2bfloat16(v.y - __bfloat162float(h1));
            hi[i] = __nv_bfloat162(h0, h1);
            lo[i] = __nv_bfloat162(l0, l1);
        }
    } else {
        __nv_bfloat162 z = __nv_bfloat162(__float2bfloat16(0.f), __float2bfloat16(0.f));
        for (int i = threadIdx.x; i < DM / 2; i += 128) { hi[i] = z; lo[i] = z; }
    }
}

// ---------------- Weight transpose + split: src [E][R][C] -> out [E][C][R] ----------------
template <int WSEL, int R, int C>
__global__ void transpose_split_kernel(const float* __restrict__ src) {
    __shared__ float t[32][33];
    const int e = blockIdx.z;
    const int c0 = blockIdx.x * 32, r0 = blockIdx.y * 32;
    const float* s = src + (size_t)e * R * C;
    __nv_bfloat16* hi = (WSEL == 0 ? g_W1hi : g_W2hi) + (size_t)e * R * C;
    __nv_bfloat16* lo = (WSEL == 0 ? g_W1lo : g_W2lo) + (size_t)e * R * C;
#pragma unroll
    for (int i = 0; i < 4; i++)
        t[threadIdx.y + 8*i][threadIdx.x] = s[(size_t)(r0 + threadIdx.y + 8*i) * C + c0 + threadIdx.x];
    __syncthreads();
#pragma unroll
    for (int i = 0; i < 4; i++) {
        int oc = c0 + threadIdx.y + 8*i;
        float v = t[threadIdx.x][threadIdx.y + 8*i];
        __nv_bfloat16 h = __float2bfloat16(v);
        size_t o = (size_t)oc * R + r0 + threadIdx.x;
        hi[o] = h;
        lo[o] = __float2bfloat16(v - __bfloat162float(h));
    }
}

// ---------------- 4/5) HMMA bf16-split GEMM ----------------
// CTA tile 128x128, K-chunk 32, 256 thr, warps 4(M)x2(N), warp tile 32x64.
// 3 products: AhiBhi + AhiBlo + AloBhi.
// PHASE 0: H = gelu(X @ W1t^T) -> bf16 hi/lo   (KD=1024, ND=2048)
// PHASE 1: Y = H @ W2t^T -> fp32               (KD=2048, ND=1024)
#define PITCH   80                    // bytes/row: 20 words -> conflict-free ldmatrix
#define TILE_SM (128 * PITCH)         // 10240 B
#define STAGE_SM (4 * TILE_SM)        // 40960 B
#define SMEMD   (2 * STAGE_SM)        // 81920 B

template <int KD, int ND, int PHASE>
__global__ __launch_bounds__(256, 2) void mma_gemm_kernel() {
    extern __shared__ __align__(128) char dsm[];
    const uint32_t smem0 = smem_u32(dsm);

    const int e  = blockIdx.z;
    const int m0 = blockIdx.y * 128;
    const int n0 = blockIdx.x * 128;
    const int tid = threadIdx.x;
    const int lane = tid & 31, wid = tid >> 5;
    const int wm = wid & 3, wn = wid >> 2;     // warp -> (row 32*wm, col 64*wn)

    const char* Ahi = (const char*)((PHASE == 0 ? g_Xhi : g_Hhi) + ((size_t)e * CAP + m0) * KD);
    const char* Alo = (const char*)((PHASE == 0 ? g_Xlo : g_Hlo) + ((size_t)e * CAP + m0) * KD);
    const char* Bhi = (const char*)((PHASE == 0 ? g_W1hi : g_W2hi) + ((size_t)e * ND + n0) * KD);
    const char* Blo = (const char*)((PHASE == 0 ? g_W1lo : g_W2lo) + ((size_t)e * ND + n0) * KD);

    float acc[2][8][4];
#pragma unroll
    for (int a = 0; a < 2; a++)
#pragma unroll
        for (int b = 0; b < 8; b++)
#pragma unroll
            for (int q = 0; q < 4; q++) acc[a][b][q] = 0.f;

    // chunk loader: 4 tiles x 128 rows x 64B; 2 cp16 per thread per tile
    const int lrowA = tid >> 2, lseg = tid & 3;   // row pair base, 16B segment
    auto load_chunk = [&](int c, int s) {
        const uint32_t buf = smem0 + s * STAGE_SM;
        const char* srcs[4] = { Ahi, Alo, Bhi, Blo };
#pragma unroll
        for (int t = 0; t < 4; t++) {
            const char* src = srcs[t] + (size_t)c * 64;
            const uint32_t tb = buf + t * TILE_SM;
#pragma unroll
            for (int j = 0; j < 2; j++) {
                int row = lrowA + 64 * j;
                cp16(tb + row * PITCH + lseg * 16, src + (size_t)row * (KD * 2) + lseg * 16);
            }
        }
        CP_COMMIT();
    };

    const int NC = KD / 32;
    load_chunk(0, 0);
    load_chunk(1, 1);

    // ldmatrix lane addressing (same pattern for A and B x4 loads)
    const int lrow = lane & 15;
    const int lkb  = ((lane >> 4) & 1) * 16;   // +8 elems = +16B

    for (int c = 0; c < NC; c++) {
        const int s = c & 1;
        if (c == NC - 1) cp_wait<0>(); else cp_wait<1>();
        __syncthreads();

        const uint32_t sAh = smem0 + s * STAGE_SM;
        const uint32_t sAl = sAh + TILE_SM;
        const uint32_t sBh = sAh + 2 * TILE_SM;
        const uint32_t sBl = sAh + 3 * TILE_SM;

#pragma unroll
        for (int kk = 0; kk < 2; kk++) {
            const int kb = kk * 32 + lkb;
            uint32_t ah[2][4], al[2][4];
#pragma unroll
            for (int mt = 0; mt < 2; mt++) {
                const uint32_t ro = (wm * 32 + mt * 16 + lrow) * PITCH + kb;
                ldsm4(ah[mt], sAh + ro);
                ldsm4(al[mt], sAl + ro);
            }
#pragma unroll
            for (int g = 0; g < 4; g++) {
                uint32_t bh[4], bl[4];
                const uint32_t ro = (wn * 64 + g * 16 + lrow) * PITCH + kb;
                ldsm4(bh, sBh + ro);
                ldsm4(bl, sBl + ro);
#pragma unroll
                for (int mt = 0; mt < 2; mt++) {
                    mma16816(acc[mt][2*g],   ah[mt], bh[0], bh[2]);
                    mma16816(acc[mt][2*g],   ah[mt], bl[0], bl[2]);
                    mma16816(acc[mt][2*g],   al[mt], bh[0], bh[2]);
                    mma16816(acc[mt][2*g+1], ah[mt], bh[1], bh[3]);
                    mma16816(acc[mt][2*g+1], ah[mt], bl[1], bl[3]);
                    mma16816(acc[mt][2*g+1], al[mt], bh[1], bh[3]);
                }
            }
        }
        __syncthreads();
        if (c + 2 < NC) load_chunk(c + 2, s);
    }

    // -------- epilogue --------
#pragma unroll
    for (int mt = 0; mt < 2; mt++) {
#pragma unroll
        for (int h = 0; h < 2; h++) {
            const int row = m0 + wm * 32 + mt * 16 + (lane >> 2) + 8 * h;
            const int colb = n0 + wn * 64 + 2 * (lane & 3);
            if (PHASE == 0) {
                __nv_bfloat162* hp = (__nv_bfloat162*)(g_Hhi + ((size_t)e * CAP + row) * DFF + colb);
                __nv_bfloat162* lp = (__nv_bfloat162*)(g_Hlo + ((size_t)e * CAP + row) * DFF + colb);
#pragma unroll
                for (int nt = 0; nt < 8; nt++) {
                    float v0 = gelu_f(acc[mt][nt][2*h]);
                    float v1 = gelu_f(acc[mt][nt][2*h + 1]);
                    __nv_bfloat16 h0 = __float2bfloat16(v0), h1 = __float2bfloat16(v1);
                    __nv_bfloat16 l0 = __float2bfloat16(v0 - __bfloat162float(h0));
                    __nv_bfloat16 l1 = __float2bfloat16(v1 - __bfloat162float(h1));
                    hp[nt * 4] = __nv_bfloat162(h0, h1);   // nt*8 cols / 2
                    lp[nt * 4] = __nv_bfloat162(l0, l1);
                }
            } else {
                float2* yp = (float2*)(g_Y + ((size_t)e * CAP + row) * DM + colb);
#pragma unroll
                for (int nt = 0; nt < 8; nt++)
                    yp[nt * 4] = make_float2(acc[mt][nt][2*h], acc[mt][nt][2*h + 1]);
            }
        }
    }
}

// ---------------- 6) Combine ----------------
__global__ void combine_kernel(float* __restrict__ out) {
    const int t = blockIdx.x;
    const int s0 = g_slot[2*t], s1 = g_slot[2*t+1];
    const float w0 = g_wt[2*t], w1 = g_wt[2*t+1];
    float4* o = ((float4*)out) + (size_t)t * (DM / 4);
    const float4* Y4 = (const float4*)g_Y;
    for (int i = threadIdx.x; i < DM / 4; i += blockDim.x) {
        float4 r = make_float4(0.f, 0.f, 0.f, 0.f);
        if (s0 >= 0) {
            float4 y = Y4[(size_t)s0 * (DM/4) + i];
            r.x += w0*y.x; r.y += w0*y.y; r.z += w0*y.z; r.w += w0*y.w;
        }
        if (s1 >= 0) {
            float4 y = Y4[(size_t)s1 * (DM/4) + i];
            r.x += w1*y.x; r.y += w1*y.y; r.z += w1*y.z; r.w += w1*y.w;
        }
        o[i] = r;
    }
}

// ---------------- Launch ----------------
extern "C" void kernel_launch(void* const* d_in, const int* in_sizes, int n_in,
                              void* d_out, int out_size) {
    (void)in_sizes; (void)n_in; (void)out_size;
    const float* x  = (const float*)d_in[0];
    const float* gw = (const float*)d_in[1];
    const float* w1 = (const float*)d_in[2];   // [16,1024,2048]
    const float* w2 = (const float*)d_in[3];   // [16,2048,1024]
    float* out = (float*)d_out;

    cudaFuncSetAttribute(mma_gemm_kernel<DM,  DFF, 0>, cudaFuncAttributeMaxDynamicSharedMemorySize, SMEMD);
    cudaFuncSetAttribute(mma_gemm_kernel<DFF, DM,  1>, cudaFuncAttributeMaxDynamicSharedMemorySize, SMEMD);

    gate_kernel<<<T_TOK / 8, 256>>>(x, gw);
    rank_kernel<<<NE, 256>>>();
    gather_split_kernel<<<EC, 128>>>(x);
    transpose_split_kernel<0, DM,  DFF><<<dim3(DFF/32, DM/32,  NE), dim3(32, 8)>>>(w1);
    transpose_split_kernel<1, DFF, DM ><<<dim3(DM/32,  DFF/32, NE), dim3(32, 8)>>>(w2);
    mma_gemm_kernel<DM,  DFF, 0><<<dim3(DFF/128, CAP/128, NE), 256, SMEMD>>>();
    mma_gemm_kernel<DFF, DM,  1><<<dim3(DM/128,  CAP/128, NE), 256, SMEMD>>>();
    combine_kernel<<<T_TOK, 256>>>(out);
}